// round 5
// baseline (speedup 1.0000x reference)
#include <cuda_runtime.h>
#include <math.h>

#define B_ 256
#define T_ 256
#define F_ 128
#define H_ 512
#define BT (B_*T_)

// ---------------- scratch (static __device__ allocations; no cudaMalloc) ----
__device__ float g_xm[(size_t)BT * 256];        // [BT][256] = x_rep | m
__device__ float g_gamma_h[(size_t)BT * H_];    // [BT][512]
__device__ float g_gi[(size_t)BT * 1536];       // [BT][1536] gi_pre (x/m part + b_ih)
__device__ float g_Wpack[6 * H_ * H_];          // [6][512][512]
__device__ float g_W2[1536 * 256];              // [1536][256]
__device__ float g_h[2][B_ * H_];               // ping-pong hidden state

// ---------------- f32x2 helpers --------------------------------------------
#define FMA2(d, a, b) asm("fma.rn.f32x2 %0, %1, %2, %0;" : "+l"(d) : "l"(a), "l"(b))
#define UNPK2(lo, hi, v) asm("mov.b64 {%0, %1}, %2;" : "=f"(lo), "=f"(hi) : "l"(v))

// ---------------- pack kernels ---------------------------------------------
__global__ void __launch_bounds__(256) pack_w2_kernel(const float* __restrict__ W_ih) {
    int idx = blockIdx.x * 256 + threadIdx.x;       // 1536*256
    int row = idx >> 8, k = idx & 255;
    // A rows are [x_rep(128) | m(128)]; W_ih cols: [x(0:128) | h(128:640) | m(640:768)]
    float v = (k < 128) ? W_ih[row * 768 + k] : W_ih[row * 768 + 512 + k];
    g_W2[idx] = v;
}

__global__ void __launch_bounds__(256) pack_wp_kernel(const float* __restrict__ W_ih,
                                                      const float* __restrict__ W_hh) {
    int idx = blockIdx.x * 256 + threadIdx.x;       // 6*512*512
    int k = idx & 511;
    int j = (idx >> 9) & 511;
    int g = idx >> 18;
    float v = (g < 3) ? W_ih[(g * 512 + j) * 768 + 128 + k]
                      : W_hh[((g - 3) * 512 + j) * 512 + k];
    g_Wpack[idx] = v;
}

__global__ void __launch_bounds__(256) zero_h_kernel() {
    g_h[0][blockIdx.x * 256 + threadIdx.x] = 0.0f;
}

// ---------------- elementwise: x_rep / m packing ----------------------------
__global__ void __launch_bounds__(256) xm_kernel(const float* __restrict__ values,
                          const float* __restrict__ masks,
                          const float* __restrict__ deltas,
                          const float* __restrict__ emean,
                          const float* __restrict__ xlocf,
                          const float* __restrict__ wx,
                          const float* __restrict__ bx) {
    int idx = blockIdx.x * 256 + threadIdx.x;       // BT*F
    int f = idx & 127;
    int r = idx >> 7;
    float d = deltas[idx];
    float a = d * wx[f] + bx[f];
    float gx = (a > 0.0f) ? expf(-a) : 1.0f;
    float m = masks[idx];
    float xh = gx * xlocf[idx] + (1.0f - gx) * emean[f];
    float xr = m * values[idx] + (1.0f - m) * xh;
    g_xm[(size_t)r * 256 + f] = xr;
    g_xm[(size_t)r * 256 + 128 + f] = m;
}

// ---------------- generic precompute GEMM: C = f(A @ W^T + bias) ------------
// BM=64, BN=64, Kc=16, 256 threads, per-thread 4x4 via f32x2 pairs.
// which==0: gamma_h = exp(-relu(deltas @ Wh^T + bh))    [BT,128]x[512,128]^T
// which==1: gi_pre  = g_xm @ g_W2^T + b_ih              [BT,256]x[1536,256]^T
// All scratch pointers resolved in DEVICE code (no cudaGetSymbolAddress on host).
__global__ void __launch_bounds__(256) gemm_f2_kernel(const float* __restrict__ Ap,
                               const float* __restrict__ Wp,
                               const float* __restrict__ bias,
                               int which) {
    const float* __restrict__ A;
    const float* __restrict__ W;
    float* __restrict__ C;
    int N, K;
    if (which == 0) { A = Ap;   W = Wp;   C = g_gamma_h; N = 512;  K = 128; }
    else            { A = g_xm; W = g_W2; C = g_gi;      N = 1536; K = 256; }

    __shared__ __align__(16) float As[16 * 130];    // [k][2*row] duplicated, stride 130
    __shared__ __align__(16) float Bs[16 * 66];     // [k][col], stride 66
    const int tid = threadIdx.x;
    const int m0 = blockIdx.y * 64;
    const int n0 = blockIdx.x * 64;
    const int lr = tid >> 2;            // 0..63 tile row for loads
    const int kq = (tid & 3) << 2;      // k sub-offset (0,4,8,12)
    const int ty = tid >> 4, tx = tid & 15;

    unsigned long long acc[4][2];
#pragma unroll
    for (int r = 0; r < 4; r++) { acc[r][0] = 0ull; acc[r][1] = 0ull; }

    for (int k0 = 0; k0 < K; k0 += 16) {
        float4 av = *(const float4*)(A + (size_t)(m0 + lr) * K + k0 + kq);
        float4 bv = *(const float4*)(W + (size_t)(n0 + lr) * K + k0 + kq);
        __syncthreads();
        As[(kq + 0) * 130 + 2 * lr] = av.x; As[(kq + 0) * 130 + 2 * lr + 1] = av.x;
        As[(kq + 1) * 130 + 2 * lr] = av.y; As[(kq + 1) * 130 + 2 * lr + 1] = av.y;
        As[(kq + 2) * 130 + 2 * lr] = av.z; As[(kq + 2) * 130 + 2 * lr + 1] = av.z;
        As[(kq + 3) * 130 + 2 * lr] = av.w; As[(kq + 3) * 130 + 2 * lr + 1] = av.w;
        Bs[(kq + 0) * 66 + lr] = bv.x;
        Bs[(kq + 1) * 66 + lr] = bv.y;
        Bs[(kq + 2) * 66 + lr] = bv.z;
        Bs[(kq + 3) * 66 + lr] = bv.w;
        __syncthreads();
#pragma unroll
        for (int kk = 0; kk < 16; kk++) {
            unsigned long long b01 = *(const unsigned long long*)&Bs[kk * 66 + tx * 4];
            unsigned long long b23 = *(const unsigned long long*)&Bs[kk * 66 + tx * 4 + 2];
#pragma unroll
            for (int r = 0; r < 4; r++) {
                unsigned long long ad =
                    *(const unsigned long long*)&As[kk * 130 + (ty * 4 + r) * 2];
                FMA2(acc[r][0], ad, b01);
                FMA2(acc[r][1], ad, b23);
            }
        }
    }
    const int n = n0 + tx * 4;
    float b0v = bias[n], b1v = bias[n + 1], b2v = bias[n + 2], b3v = bias[n + 3];
#pragma unroll
    for (int r = 0; r < 4; r++) {
        int m = m0 + ty * 4 + r;
        float4 v;
        UNPK2(v.x, v.y, acc[r][0]);
        UNPK2(v.z, v.w, acc[r][1]);
        v.x += b0v; v.y += b1v; v.z += b2v; v.w += b3v;
        if (which == 0) {
            v.x = (v.x > 0.0f) ? expf(-v.x) : 1.0f;
            v.y = (v.y > 0.0f) ? expf(-v.y) : 1.0f;
            v.z = (v.z > 0.0f) ? expf(-v.z) : 1.0f;
            v.w = (v.w > 0.0f) ? expf(-v.w) : 1.0f;
        }
        *(float4*)(C + (size_t)m * N + n) = v;
    }
}

// ---------------- fused per-timestep kernel ---------------------------------
// Block: 32 batch rows x 32 h-cols x 6 gates (192 GEMM cols), K = 512.
// Grid: (H/32=16, B/32=8) = 128 blocks, 256 threads.
__global__ void __launch_bounds__(256) step_kernel(int t, const float* __restrict__ b_hh,
                            float* __restrict__ out) {
    __shared__ __align__(16) float Ws[32 * 194];    // [k][c] stride 194 (also epilogue S)
    __shared__ __align__(16) float Ad[32 * 66];     // [k][2*row] duplicated
    const int tid = threadIdx.x;
    const int h0 = blockIdx.x * 32;
    const int b0 = blockIdx.y * 32;
    const float* __restrict__ hin = g_h[t & 1];
    float* __restrict__ hout = g_h[(t + 1) & 1];

    const int cg = tid & 31, rg = tid >> 5;
    const int ar = tid >> 3, akq = (tid & 7) << 2;  // A-load mapping

    unsigned long long acc[4][3];
#pragma unroll
    for (int rr = 0; rr < 4; rr++) { acc[rr][0] = 0ull; acc[rr][1] = 0ull; acc[rr][2] = 0ull; }

    for (int k0 = 0; k0 < 512; k0 += 32) {
        float4 hv = *(const float4*)(hin + (b0 + ar) * H_ + k0 + akq);
        float4 gv = *(const float4*)(g_gamma_h +
                       ((size_t)(b0 + ar) * T_ + t) * H_ + k0 + akq);
        float4 wv[6];
        int wc[6], wk[6];
#pragma unroll
        for (int i = 0; i < 6; i++) {
            int f = i * 256 + tid;
            wc[i] = f >> 3;
            wk[i] = (f & 7) << 2;
            int g = wc[i] >> 5, jh = wc[i] & 31;
            wv[i] = *(const float4*)(g_Wpack +
                        ((size_t)g * H_ + h0 + jh) * 512 + k0 + wk[i]);
        }
        __syncthreads();
        hv.x *= gv.x; hv.y *= gv.y; hv.z *= gv.z; hv.w *= gv.w;
        Ad[(akq + 0) * 66 + 2 * ar] = hv.x; Ad[(akq + 0) * 66 + 2 * ar + 1] = hv.x;
        Ad[(akq + 1) * 66 + 2 * ar] = hv.y; Ad[(akq + 1) * 66 + 2 * ar + 1] = hv.y;
        Ad[(akq + 2) * 66 + 2 * ar] = hv.z; Ad[(akq + 2) * 66 + 2 * ar + 1] = hv.z;
        Ad[(akq + 3) * 66 + 2 * ar] = hv.w; Ad[(akq + 3) * 66 + 2 * ar + 1] = hv.w;
#pragma unroll
        for (int i = 0; i < 6; i++) {
            Ws[(wk[i] + 0) * 194 + wc[i]] = wv[i].x;
            Ws[(wk[i] + 1) * 194 + wc[i]] = wv[i].y;
            Ws[(wk[i] + 2) * 194 + wc[i]] = wv[i].z;
            Ws[(wk[i] + 3) * 194 + wc[i]] = wv[i].w;
        }
        __syncthreads();
#pragma unroll
        for (int kk = 0; kk < 32; kk++) {
            unsigned long long bp0 = *(const unsigned long long*)&Ws[kk * 194 + 2 * cg];
            unsigned long long bp1 = *(const unsigned long long*)&Ws[kk * 194 + 2 * cg + 64];
            unsigned long long bp2 = *(const unsigned long long*)&Ws[kk * 194 + 2 * cg + 128];
#pragma unroll
            for (int rr = 0; rr < 4; rr++) {
                unsigned long long ad =
                    *(const unsigned long long*)&Ad[kk * 66 + (rg * 4 + rr) * 2];
                FMA2(acc[rr][0], ad, bp0);
                FMA2(acc[rr][1], ad, bp1);
                FMA2(acc[rr][2], ad, bp2);
            }
        }
    }
    __syncthreads();
    // dump accumulators into Ws as S[row][c] (stride 194)
#pragma unroll
    for (int rr = 0; rr < 4; rr++) {
        int row = rg * 4 + rr;
#pragma unroll
        for (int j = 0; j < 3; j++) {
            *(unsigned long long*)&Ws[row * 194 + 2 * cg + 64 * j] = acc[rr][j];
        }
    }
    __syncthreads();
    // gate nonlinearity + state update: 32x32 items, 4 per thread
#pragma unroll
    for (int it = 0; it < 4; it++) {
        int item = it * 256 + tid;
        int row = item >> 5, jh = item & 31;
        int gb = b0 + row, gj = h0 + jh;
        size_t ridx = (size_t)gb * T_ + t;
        const float* S = &Ws[row * 194 + jh];
        float u_r = S[0],  u_z = S[32],  u_n = S[64];
        float w_r = S[96], w_z = S[128], w_n = S[160];
        const float* gi = g_gi + ridx * 1536 + gj;
        float ir = gi[0]    + u_r;
        float iz = gi[512]  + u_z;
        float in_ = gi[1024] + u_n;
        float hr = w_r + b_hh[gj];
        float hz = w_z + b_hh[512 + gj];
        float hn = w_n + b_hh[1024 + gj];
        float hd = hin[gb * H_ + gj] * g_gamma_h[ridx * H_ + gj];
        float r = 1.0f / (1.0f + expf(-(ir + hr)));
        float z = 1.0f / (1.0f + expf(-(iz + hz)));
        float n = tanhf(in_ + r * hn);
        float hvn = (1.0f - z) * n + z * hd;
        hout[gb * H_ + gj] = hvn;
        out[ridx * H_ + gj] = hvn;
        if (t == T_ - 1) out[(size_t)BT * H_ + (size_t)gb * H_ + gj] = hvn;
    }
}

// ---------------- launch ----------------------------------------------------
// Pure kernel launches only: no CUDA API calls of any other kind, so graph
// capture sees exactly 262 launch nodes.
extern "C" void kernel_launch(void* const* d_in, const int* in_sizes, int n_in,
                              void* d_out, int out_size) {
    const float* values = (const float*)d_in[0];
    const float* masks  = (const float*)d_in[1];
    const float* deltas = (const float*)d_in[2];
    const float* emean  = (const float*)d_in[3];
    const float* xlocf  = (const float*)d_in[4];
    const float* wx     = (const float*)d_in[5];
    const float* bx     = (const float*)d_in[6];
    const float* Wh     = (const float*)d_in[7];
    const float* bh     = (const float*)d_in[8];
    const float* W_ih   = (const float*)d_in[9];
    const float* W_hh   = (const float*)d_in[10];
    const float* b_ih   = (const float*)d_in[11];
    const float* b_hh   = (const float*)d_in[12];
    float* out = (float*)d_out;

    pack_w2_kernel<<<(1536 * 256) / 256, 256>>>(W_ih);
    pack_wp_kernel<<<(6 * 512 * 512) / 256, 256>>>(W_ih, W_hh);
    xm_kernel<<<(BT * F_) / 256, 256>>>(values, masks, deltas, emean, xlocf, wx, bx);
    zero_h_kernel<<<(B_ * H_) / 256, 256>>>();
    // gamma_h = exp(-relu(deltas @ Wh^T + bh)) : [BT,128] x [512,128]^T
    gemm_f2_kernel<<<dim3(512 / 64, BT / 64), 256>>>(deltas, Wh, bh, 0);
    // gi_pre = xm @ W2^T + b_ih : [BT,256] x [1536,256]^T (A/W resolved in-kernel)
    gemm_f2_kernel<<<dim3(1536 / 64, BT / 64), 256>>>(nullptr, nullptr, b_ih, 1);
    for (int t = 0; t < T_; t++)
        step_kernel<<<dim3(16, 8), 256>>>(t, b_hh, out);
}